// round 2
// baseline (speedup 1.0000x reference)
#include <cuda_runtime.h>
#include <cuda_bf16.h>

// Problem constants (fixed by the dataset instance)
#define NROWS  4096
#define DDIM   1024
#define NCLS   512
#define NNEGS  3679
#define HHALF  7534592u        // n/2 for threefry lane pairing, n = 4096*3679
#define MARGINF 0.15f

// Scratch (static __device__ arrays: allocation-free)
__device__ float g_xn[NROWS * DDIM];     // normalized samples, fp32 (16 MB)
__device__ float g_dpos[NROWS * 8];      // per-row positive distances, slots 0..p-1

// ---------------------------------------------------------------------------
// Threefry-2x32-20, key (0, 42), exact JAX semantics.
// flat index f in [0, n); lane = f or f-h; pair counts (lane, lane+h).
// ---------------------------------------------------------------------------
__device__ __forceinline__ float tf_uniform(unsigned f) {
    const unsigned ks1 = 42u;
    const unsigned ks2 = 0x1BD11BDAu ^ 42u;   // ks0 ^ ks1 ^ 0x1BD11BDA, ks0 = 0
    unsigned lane = (f < HHALF) ? f : (f - HHALF);
    unsigned x0 = lane;                 // + ks0 (= 0)
    unsigned x1 = lane + HHALF + ks1;   // + ks1
#define TFR(r) { x0 += x1; x1 = (x1 << (r)) | (x1 >> (32 - (r))); x1 ^= x0; }
    TFR(13) TFR(15) TFR(26) TFR(6)   x0 += ks1; x1 += ks2 + 1u;
    TFR(17) TFR(29) TFR(16) TFR(24)  x0 += ks2; x1 += 0u  + 2u;
    TFR(13) TFR(15) TFR(26) TFR(6)   x0 += 0u;  x1 += ks1 + 3u;
    TFR(17) TFR(29) TFR(16) TFR(24)  x0 += ks1; x1 += ks2 + 4u;
    TFR(13) TFR(15) TFR(26) TFR(6)   x0 += ks2; x1 += 0u  + 5u;
#undef TFR
    unsigned bits = (f < HHALF) ? x0 : x1;
    return __uint_as_float((bits >> 9) | 0x3F800000u) - 1.0f;
}

// ---------------------------------------------------------------------------
// Kernel 1: row L2-normalize.  grid = NROWS blocks, 256 threads.
// ---------------------------------------------------------------------------
__global__ void normalize_kernel(const float* __restrict__ x) {
    int row = blockIdx.x;
    int t = threadIdx.x;
    const float4* xin = (const float4*)(x + (size_t)row * DDIM);
    float4 v = xin[t];
    float ss = v.x * v.x + v.y * v.y + v.z * v.z + v.w * v.w;
    #pragma unroll
    for (int o = 16; o; o >>= 1) ss += __shfl_down_sync(0xffffffffu, ss, o);
    __shared__ float ws[8];
    if ((t & 31) == 0) ws[t >> 5] = ss;
    __syncthreads();
    if (t < 8) {
        float s2 = ws[t];
        #pragma unroll
        for (int o = 4; o; o >>= 1) s2 += __shfl_down_sync(0xffu, s2, o);
        if (t == 0) ws[0] = s2;
    }
    __syncthreads();
    float scale = 1.0f / fmaxf(sqrtf(ws[0]), 1e-8f);
    v.x *= scale; v.y *= scale; v.z *= scale; v.w *= scale;
    ((float4*)(g_xn + (size_t)row * DDIM))[t] = v;
}

// ---------------------------------------------------------------------------
// Kernel 2: positive distances within each class (8x8 upper-triangle dots).
// grid = NCLS blocks, 256 threads (8 warps; warp w does pairs w, w+8, w+16, w+24)
// ---------------------------------------------------------------------------
__global__ void posdist_kernel() {
    int cls = blockIdx.x;
    __shared__ float sm[8][DDIM];     // 32 KB
    int t = threadIdx.x;
    const float4* src = (const float4*)(g_xn + (size_t)cls * 8 * DDIM);
    float4* dst = (float4*)(&sm[0][0]);
    #pragma unroll
    for (int idx = t; idx < 8 * DDIM / 4; idx += 256) dst[idx] = src[idx];
    __syncthreads();
    int w = t >> 5, lane = t & 31;
    for (int q = w; q < 28; q += 8) {
        // map q -> (a, b), a < b < 8
        int a = 0, rem = q;
        while (rem >= 7 - a) { rem -= 7 - a; a++; }
        int b = a + 1 + rem;
        float s = 0.f;
        for (int e = lane; e < DDIM; e += 32) s += sm[a][e] * sm[b][e];
        #pragma unroll
        for (int o = 16; o; o >>= 1) s += __shfl_down_sync(0xffffffffu, s, o);
        if (lane == 0) g_dpos[(cls * 8 + a) * 8 + (b - a - 1)] = 1.0f - s;
    }
}

// ---------------------------------------------------------------------------
// Kernel 3: zero the output
// ---------------------------------------------------------------------------
__global__ void zero_kernel(float* out, int n) {
    int i = blockIdx.x * blockDim.x + threadIdx.x;
    if (i < n) out[i] = 0.0f;
}

// ---------------------------------------------------------------------------
// Kernel 4: fused Gram + triplet-loss epilogue.
// grid (32, 32): blockIdx.y = row tile (128 rows), blockIdx.x = col tile.
// 256 threads, each computes an 8x8 microtile (classic SGEMM), then the
// epilogue computes the per-element hinge terms and reduces.
// ---------------------------------------------------------------------------
__global__ __launch_bounds__(256, 2) void loss_kernel(float* __restrict__ out) {
    __shared__ float As[16][132];
    __shared__ float Bs[16][132];
    __shared__ float Dp[128][8];
    __shared__ float red[8];

    int tid = threadIdx.x;
    int tx = tid & 15, ty = tid >> 4;
    int rowA = blockIdx.y * 128;
    int rowB = blockIdx.x * 128;

    // stage positive-distance table for this row tile
    {
        int r = tid >> 1, half = tid & 1;
        float4 v = *(const float4*)&g_dpos[(rowA + r) * 8 + half * 4];
        *(float4*)&Dp[r][half * 4] = v;
    }

    float acc[8][8];
    #pragma unroll
    for (int a = 0; a < 8; a++)
        #pragma unroll
        for (int b = 0; b < 8; b++) acc[a][b] = 0.f;

    for (int k0 = 0; k0 < DDIM; k0 += 16) {
        __syncthreads();   // also covers the Dp staging on iter 0
        #pragma unroll
        for (int rep = 0; rep < 2; rep++) {
            int idx = tid + rep * 256;       // 0..511
            int r = idx >> 2, c4 = idx & 3;  // r: 0..127, c4: 0..3
            float4 va = *(const float4*)&g_xn[(size_t)(rowA + r) * DDIM + k0 + c4 * 4];
            As[c4 * 4 + 0][r] = va.x; As[c4 * 4 + 1][r] = va.y;
            As[c4 * 4 + 2][r] = va.z; As[c4 * 4 + 3][r] = va.w;
            float4 vb = *(const float4*)&g_xn[(size_t)(rowB + r) * DDIM + k0 + c4 * 4];
            Bs[c4 * 4 + 0][r] = vb.x; Bs[c4 * 4 + 1][r] = vb.y;
            Bs[c4 * 4 + 2][r] = vb.z; Bs[c4 * 4 + 3][r] = vb.w;
        }
        __syncthreads();
        #pragma unroll
        for (int k = 0; k < 16; k++) {
            float a[8], b[8];
            *(float4*)&a[0] = *(const float4*)&As[k][ty * 8];
            *(float4*)&a[4] = *(const float4*)&As[k][ty * 8 + 4];
            *(float4*)&b[0] = *(const float4*)&Bs[k][tx * 8];
            *(float4*)&b[4] = *(const float4*)&Bs[k][tx * 8 + 4];
            #pragma unroll
            for (int p2 = 0; p2 < 8; p2++)
                #pragma unroll
                for (int q2 = 0; q2 < 8; q2++)
                    acc[p2][q2] += a[p2] * b[q2];
        }
    }

    // Spill accumulators to a dynamically-indexed local array so the epilogue
    // loops can stay rolled (keeps the threefry code from being emitted 64x).
    float accl[64];
    #pragma unroll
    for (int a = 0; a < 8; a++)
        #pragma unroll
        for (int b = 0; b < 8; b++) accl[a * 8 + b] = acc[a][b];

    float lsum = 0.f;
    #pragma unroll 1
    for (int r = 0; r < 8; r++) {
        int i = rowA + ty * 8 + r;
        int pi = 7 - (i & 7);
        if (pi == 0) continue;            // row has no positives -> skipped
        int c = i >> 3;
        float pf = (float)pi;
        #pragma unroll 1
        for (int q = 0; q < 8; q++) {
            int j = rowB + tx * 8 + q;
            int cj = j >> 3;
            if (cj == c) continue;        // same class: not a negative
            int dd = abs(c - cj);
            int before = max(0, c - dd) + max(0, (NCLS - 1) - c - dd)
                       + ((cj > c && c >= dd) ? 1 : 0);
            int t = (before << 3) + (j & 7);
            if (t >= NNEGS) continue;     // not among the 3679 mined negatives
            float u = tf_uniform((unsigned)(i * NNEGS + t));
            int ridx = min((int)(u * pf), pi - 1);
            // term = d_pos - d_neg + M = dpos + s_neg + (M - 1)
            float term = Dp[ty * 8 + r][ridx] + accl[r * 8 + q] + (MARGINF - 1.0f);
            lsum += fmaxf(term, 0.0f);
        }
    }

    // block reduction -> one atomicAdd per CTA
    #pragma unroll
    for (int o = 16; o; o >>= 1) lsum += __shfl_down_sync(0xffffffffu, lsum, o);
    if ((tid & 31) == 0) red[tid >> 5] = lsum;
    __syncthreads();
    if (tid < 8) {
        float s2 = red[tid];
        #pragma unroll
        for (int o = 4; o; o >>= 1) s2 += __shfl_down_sync(0xffu, s2, o);
        if (tid == 0) atomicAdd(out, s2);
    }
}

// ---------------------------------------------------------------------------
extern "C" void kernel_launch(void* const* d_in, const int* in_sizes, int n_in,
                              void* d_out, int out_size) {
    const float* samples = (const float*)d_in[0];
    float* out = (float*)d_out;

    normalize_kernel<<<NROWS, 256>>>(samples);
    posdist_kernel<<<NCLS, 256>>>();
    zero_kernel<<<(out_size + 255) / 256, 256>>>(out, out_size);
    dim3 grid(NROWS / 128, NROWS / 128);
    loss_kernel<<<grid, 256>>>(out);
}

// round 3
// speedup vs baseline: 1.0026x; 1.0026x over previous
#include <cuda_runtime.h>
#include <cuda_bf16.h>

// Problem constants (fixed by the dataset instance)
#define NROWS  4096
#define DDIM   1024
#define NCLS   512
#define NNEGS  3679
#define HHALF  7534592u        // n/2 for threefry lane pairing, n = 4096*3679
#define MARGINF 0.15f

// Scratch (static __device__ arrays: allocation-free)
__device__ float g_xn[NROWS * DDIM];     // normalized samples, fp32 (16 MB)
__device__ float g_dpos[NROWS * 8];      // per-row positive distances, slots 0..p-1

// ---------------------------------------------------------------------------
// Threefry-2x32-20, key (0, 42), exact JAX semantics.
// flat index f in [0, n); lane = f or f-h; pair counts (lane, lane+h).
// ---------------------------------------------------------------------------
__device__ __forceinline__ float tf_uniform(unsigned f) {
    const unsigned ks1 = 42u;
    const unsigned ks2 = 0x1BD11BDAu ^ 42u;   // ks0 ^ ks1 ^ 0x1BD11BDA, ks0 = 0
    unsigned lane = (f < HHALF) ? f : (f - HHALF);
    unsigned x0 = lane;                 // + ks0 (= 0)
    unsigned x1 = lane + HHALF + ks1;   // + ks1
#define TFR(r) { x0 += x1; x1 = (x1 << (r)) | (x1 >> (32 - (r))); x1 ^= x0; }
    TFR(13) TFR(15) TFR(26) TFR(6)   x0 += ks1; x1 += ks2 + 1u;
    TFR(17) TFR(29) TFR(16) TFR(24)  x0 += ks2; x1 += 0u  + 2u;
    TFR(13) TFR(15) TFR(26) TFR(6)   x0 += 0u;  x1 += ks1 + 3u;
    TFR(17) TFR(29) TFR(16) TFR(24)  x0 += ks1; x1 += ks2 + 4u;
    TFR(13) TFR(15) TFR(26) TFR(6)   x0 += ks2; x1 += 0u  + 5u;
#undef TFR
    unsigned bits = (f < HHALF) ? x0 : x1;
    return __uint_as_float((bits >> 9) | 0x3F800000u) - 1.0f;
}

// ---------------------------------------------------------------------------
// Kernel 1: row L2-normalize.  grid = NROWS blocks, 256 threads.
// ---------------------------------------------------------------------------
__global__ void normalize_kernel(const float* __restrict__ x) {
    int row = blockIdx.x;
    int t = threadIdx.x;
    const float4* xin = (const float4*)(x + (size_t)row * DDIM);
    float4 v = xin[t];
    float ss = v.x * v.x + v.y * v.y + v.z * v.z + v.w * v.w;
    #pragma unroll
    for (int o = 16; o; o >>= 1) ss += __shfl_down_sync(0xffffffffu, ss, o);
    __shared__ float ws[8];
    if ((t & 31) == 0) ws[t >> 5] = ss;
    __syncthreads();
    if (t < 8) {
        float s2 = ws[t];
        #pragma unroll
        for (int o = 4; o; o >>= 1) s2 += __shfl_down_sync(0xffu, s2, o);
        if (t == 0) ws[0] = s2;
    }
    __syncthreads();
    float scale = 1.0f / fmaxf(sqrtf(ws[0]), 1e-8f);
    v.x *= scale; v.y *= scale; v.z *= scale; v.w *= scale;
    ((float4*)(g_xn + (size_t)row * DDIM))[t] = v;
}

// ---------------------------------------------------------------------------
// Kernel 2: positive distances within each class (8x8 upper-triangle dots).
// grid = NCLS blocks, 256 threads (8 warps; warp w does pairs w, w+8, w+16, w+24)
// ---------------------------------------------------------------------------
__global__ void posdist_kernel() {
    int cls = blockIdx.x;
    __shared__ float sm[8][DDIM];     // 32 KB
    int t = threadIdx.x;
    const float4* src = (const float4*)(g_xn + (size_t)cls * 8 * DDIM);
    float4* dst = (float4*)(&sm[0][0]);
    #pragma unroll
    for (int idx = t; idx < 8 * DDIM / 4; idx += 256) dst[idx] = src[idx];
    __syncthreads();
    int w = t >> 5, lane = t & 31;
    for (int q = w; q < 28; q += 8) {
        // map q -> (a, b), a < b < 8
        int a = 0, rem = q;
        while (rem >= 7 - a) { rem -= 7 - a; a++; }
        int b = a + 1 + rem;
        float s = 0.f;
        for (int e = lane; e < DDIM; e += 32) s += sm[a][e] * sm[b][e];
        #pragma unroll
        for (int o = 16; o; o >>= 1) s += __shfl_down_sync(0xffffffffu, s, o);
        if (lane == 0) g_dpos[(cls * 8 + a) * 8 + (b - a - 1)] = 1.0f - s;
    }
}

// ---------------------------------------------------------------------------
// Kernel 3: zero the output
// ---------------------------------------------------------------------------
__global__ void zero_kernel(float* out, int n) {
    int i = blockIdx.x * blockDim.x + threadIdx.x;
    if (i < n) out[i] = 0.0f;
}

// ---------------------------------------------------------------------------
// Kernel 4: fused Gram + triplet-loss epilogue.
// grid (32, 32): blockIdx.y = row tile (128 rows), blockIdx.x = col tile.
// 256 threads, each computes an 8x8 microtile (classic SGEMM), then the
// epilogue computes the per-element hinge terms and reduces.
// ---------------------------------------------------------------------------
__global__ __launch_bounds__(256, 2) void loss_kernel(float* __restrict__ out) {
    __shared__ float As[16][132];
    __shared__ float Bs[16][132];
    __shared__ float Dp[128][8];
    __shared__ float red[8];

    int tid = threadIdx.x;
    int tx = tid & 15, ty = tid >> 4;
    int rowA = blockIdx.y * 128;
    int rowB = blockIdx.x * 128;

    // stage positive-distance table for this row tile
    {
        int r = tid >> 1, half = tid & 1;
        float4 v = *(const float4*)&g_dpos[(rowA + r) * 8 + half * 4];
        *(float4*)&Dp[r][half * 4] = v;
    }

    float acc[8][8];
    #pragma unroll
    for (int a = 0; a < 8; a++)
        #pragma unroll
        for (int b = 0; b < 8; b++) acc[a][b] = 0.f;

    for (int k0 = 0; k0 < DDIM; k0 += 16) {
        __syncthreads();   // also covers the Dp staging on iter 0
        #pragma unroll
        for (int rep = 0; rep < 2; rep++) {
            int idx = tid + rep * 256;       // 0..511
            int r = idx >> 2, c4 = idx & 3;  // r: 0..127, c4: 0..3
            float4 va = *(const float4*)&g_xn[(size_t)(rowA + r) * DDIM + k0 + c4 * 4];
            As[c4 * 4 + 0][r] = va.x; As[c4 * 4 + 1][r] = va.y;
            As[c4 * 4 + 2][r] = va.z; As[c4 * 4 + 3][r] = va.w;
            float4 vb = *(const float4*)&g_xn[(size_t)(rowB + r) * DDIM + k0 + c4 * 4];
            Bs[c4 * 4 + 0][r] = vb.x; Bs[c4 * 4 + 1][r] = vb.y;
            Bs[c4 * 4 + 2][r] = vb.z; Bs[c4 * 4 + 3][r] = vb.w;
        }
        __syncthreads();
        #pragma unroll
        for (int k = 0; k < 16; k++) {
            float a[8], b[8];
            *(float4*)&a[0] = *(const float4*)&As[k][ty * 8];
            *(float4*)&a[4] = *(const float4*)&As[k][ty * 8 + 4];
            *(float4*)&b[0] = *(const float4*)&Bs[k][tx * 8];
            *(float4*)&b[4] = *(const float4*)&Bs[k][tx * 8 + 4];
            #pragma unroll
            for (int p2 = 0; p2 < 8; p2++)
                #pragma unroll
                for (int q2 = 0; q2 < 8; q2++)
                    acc[p2][q2] += a[p2] * b[q2];
        }
    }

    // Spill accumulators to a dynamically-indexed local array so the epilogue
    // loops can stay rolled (keeps the threefry code from being emitted 64x).
    float accl[64];
    #pragma unroll
    for (int a = 0; a < 8; a++)
        #pragma unroll
        for (int b = 0; b < 8; b++) accl[a * 8 + b] = acc[a][b];

    float lsum = 0.f;
    #pragma unroll 1
    for (int r = 0; r < 8; r++) {
        int i = rowA + ty * 8 + r;
        int pi = 7 - (i & 7);
        if (pi == 0) continue;            // row has no positives -> skipped
        int c = i >> 3;
        float pf = (float)pi;
        #pragma unroll 1
        for (int q = 0; q < 8; q++) {
            int j = rowB + tx * 8 + q;
            int cj = j >> 3;
            if (cj == c) continue;        // same class: not a negative
            int dd = abs(c - cj);
            int before = max(0, c - dd) + max(0, (NCLS - 1) - c - dd)
                       + ((cj > c && c >= dd) ? 1 : 0);
            int t = (before << 3) + (j & 7);
            if (t >= NNEGS) continue;     // not among the 3679 mined negatives
            float u = tf_uniform((unsigned)(i * NNEGS + t));
            int ridx = min((int)(u * pf), pi - 1);
            // term = d_pos - d_neg + M = dpos + s_neg + (M - 1)
            float term = Dp[ty * 8 + r][ridx] + accl[r * 8 + q] + (MARGINF - 1.0f);
            lsum += fmaxf(term, 0.0f);
        }
    }

    // block reduction -> one atomicAdd per CTA
    #pragma unroll
    for (int o = 16; o; o >>= 1) lsum += __shfl_down_sync(0xffffffffu, lsum, o);
    if ((tid & 31) == 0) red[tid >> 5] = lsum;
    __syncthreads();
    if (tid < 8) {
        float s2 = red[tid];
        #pragma unroll
        for (int o = 4; o; o >>= 1) s2 += __shfl_down_sync(0xffu, s2, o);
        if (tid == 0) atomicAdd(out, s2);
    }
}

// ---------------------------------------------------------------------------
extern "C" void kernel_launch(void* const* d_in, const int* in_sizes, int n_in,
                              void* d_out, int out_size) {
    const float* samples = (const float*)d_in[0];
    float* out = (float*)d_out;

    normalize_kernel<<<NROWS, 256>>>(samples);
    posdist_kernel<<<NCLS, 256>>>();
    zero_kernel<<<(out_size + 255) / 256, 256>>>(out, out_size);
    dim3 grid(NROWS / 128, NROWS / 128);
    loss_kernel<<<grid, 256>>>(out);
}

// round 4
// speedup vs baseline: 5.4415x; 5.4273x over previous
#include <cuda_runtime.h>
#include <cuda_bf16.h>

// Problem constants (fixed by the dataset instance)
#define NROWS  4096
#define DDIM   1024
#define NCLS   512
#define NNEGS  3679
#define HHALF  7534592u        // n/2 for threefry lane pairing, n = 4096*3679
#define MARGINF 0.15f

// Scratch (static __device__ arrays: allocation-free)
__device__ float g_xn[NROWS * DDIM];            // normalized samples, fp32 (posdist)
__device__ __nv_bfloat16 g_xb[NROWS * DDIM];    // normalized samples, bf16 (gram)
__device__ float g_dpos[NROWS * 8];             // per-row positive distances

// ---------------------------------------------------------------------------
// Threefry-2x32-20, key (0, 42), exact JAX semantics.
// ---------------------------------------------------------------------------
__device__ __forceinline__ float tf_uniform(unsigned f) {
    const unsigned ks1 = 42u;
    const unsigned ks2 = 0x1BD11BDAu ^ 42u;
    unsigned lane = (f < HHALF) ? f : (f - HHALF);
    unsigned x0 = lane;
    unsigned x1 = lane + HHALF + ks1;
#define TFR(r) { x0 += x1; x1 = (x1 << (r)) | (x1 >> (32 - (r))); x1 ^= x0; }
    TFR(13) TFR(15) TFR(26) TFR(6)   x0 += ks1; x1 += ks2 + 1u;
    TFR(17) TFR(29) TFR(16) TFR(24)  x0 += ks2; x1 += 0u  + 2u;
    TFR(13) TFR(15) TFR(26) TFR(6)   x0 += 0u;  x1 += ks1 + 3u;
    TFR(17) TFR(29) TFR(16) TFR(24)  x0 += ks1; x1 += ks2 + 4u;
    TFR(13) TFR(15) TFR(26) TFR(6)   x0 += ks2; x1 += 0u  + 5u;
#undef TFR
    unsigned bits = (f < HHALF) ? x0 : x1;
    return __uint_as_float((bits >> 9) | 0x3F800000u) - 1.0f;
}

// Per-element triplet hinge term. dp points at the 8-slot positive-distance
// row for anchor i (in shared memory); s = cos(i, j).
__device__ __forceinline__ float triplet_term(int i, int j, float s,
                                              const float* __restrict__ dp) {
    int pi = 7 - (i & 7);
    int c = i >> 3, cj = j >> 3;
    if (pi == 0 || c == cj) return 0.0f;
    int dd = abs(c - cj);
    int before = max(0, c - dd) + max(0, (NCLS - 1) - c - dd)
               + ((cj > c && c >= dd) ? 1 : 0);
    int t = (before << 3) + (j & 7);
    if (t >= NNEGS) return 0.0f;
    float u = tf_uniform((unsigned)i * NNEGS + (unsigned)t);
    int ridx = min((int)(u * (float)pi), pi - 1);
    // d_pos - d_neg + M = dp + cos + (M - 1)
    return fmaxf(dp[ridx] + s + (MARGINF - 1.0f), 0.0f);
}

// ---------------------------------------------------------------------------
// Kernel 1: row L2-normalize; writes fp32 and bf16 copies.
// ---------------------------------------------------------------------------
__global__ void normalize_kernel(const float* __restrict__ x) {
    int row = blockIdx.x;
    int t = threadIdx.x;
    const float4* xin = (const float4*)(x + (size_t)row * DDIM);
    float4 v = xin[t];
    float ss = v.x * v.x + v.y * v.y + v.z * v.z + v.w * v.w;
    #pragma unroll
    for (int o = 16; o; o >>= 1) ss += __shfl_down_sync(0xffffffffu, ss, o);
    __shared__ float ws[8];
    if ((t & 31) == 0) ws[t >> 5] = ss;
    __syncthreads();
    if (t < 8) {
        float s2 = ws[t];
        #pragma unroll
        for (int o = 4; o; o >>= 1) s2 += __shfl_down_sync(0xffu, s2, o);
        if (t == 0) ws[0] = s2;
    }
    __syncthreads();
    float scale = 1.0f / fmaxf(sqrtf(ws[0]), 1e-8f);
    v.x *= scale; v.y *= scale; v.z *= scale; v.w *= scale;
    ((float4*)(g_xn + (size_t)row * DDIM))[t] = v;
    __nv_bfloat16 b[4];
    b[0] = __float2bfloat16(v.x); b[1] = __float2bfloat16(v.y);
    b[2] = __float2bfloat16(v.z); b[3] = __float2bfloat16(v.w);
    *(uint2*)(g_xb + (size_t)row * DDIM + t * 4) = *(uint2*)b;
}

// ---------------------------------------------------------------------------
// Kernel 2: positive distances within each class (fp32, exact).
// ---------------------------------------------------------------------------
__global__ void posdist_kernel() {
    int cls = blockIdx.x;
    __shared__ float sm[8][DDIM];
    int t = threadIdx.x;
    const float4* src = (const float4*)(g_xn + (size_t)cls * 8 * DDIM);
    float4* dst = (float4*)(&sm[0][0]);
    #pragma unroll
    for (int idx = t; idx < 8 * DDIM / 4; idx += 256) dst[idx] = src[idx];
    __syncthreads();
    int w = t >> 5, lane = t & 31;
    for (int q = w; q < 28; q += 8) {
        int a = 0, rem = q;
        while (rem >= 7 - a) { rem -= 7 - a; a++; }
        int b = a + 1 + rem;
        float s = 0.f;
        for (int e = lane; e < DDIM; e += 32) s += sm[a][e] * sm[b][e];
        #pragma unroll
        for (int o = 16; o; o >>= 1) s += __shfl_down_sync(0xffffffffu, s, o);
        if (lane == 0) g_dpos[(cls * 8 + a) * 8 + (b - a - 1)] = 1.0f - s;
    }
}

__global__ void zero_kernel(float* out, int n) {
    int i = blockIdx.x * blockDim.x + threadIdx.x;
    if (i < n) out[i] = 0.0f;
}

// ---------------------------------------------------------------------------
// Kernel 4: bf16 tensor-core Gram (upper-triangular tiles only) + fused
// triplet epilogue applied in both orientations for off-diagonal tiles.
// CTA = 128x128 tile, 8 warps, each warp 64x32 via m16n8k16 mma.sync.
// ---------------------------------------------------------------------------
__global__ __launch_bounds__(256, 2) void loss_kernel(float* __restrict__ out) {
    int bx = blockIdx.x, by = blockIdx.y;
    if (bx < by) return;                    // symmetry: upper triangle only
    const bool offDiag = (bx != by);
    int rowA = by * 128, rowB = bx * 128;

    __shared__ __align__(16) __nv_bfloat16 Asm[128 * 40]; // stride 40 (80B): 5 coprime 8 -> LDSM conflict-free
    __shared__ __align__(16) __nv_bfloat16 Bsm[128 * 40];
    __shared__ float DpA[128][8];
    __shared__ float DpB[128][8];
    __shared__ float red[8];

    int tid = threadIdx.x;
    int w = tid >> 5, lane = tid & 31;
    int wr = w & 1, wc = w >> 1;            // warp tile: rows wr*64, cols wc*32
    int g = lane >> 2, t4 = lane & 3;

    // stage positive-distance tables for both tiles
    {
        int r = tid >> 1, h = tid & 1;
        *(float4*)&DpA[r][h * 4] = *(const float4*)&g_dpos[(rowA + r) * 8 + h * 4];
        *(float4*)&DpB[r][h * 4] = *(const float4*)&g_dpos[(rowB + r) * 8 + h * 4];
    }

    float acc[4][4][4];
    #pragma unroll
    for (int mt = 0; mt < 4; mt++)
        #pragma unroll
        for (int nt = 0; nt < 4; nt++)
            #pragma unroll
            for (int e = 0; e < 4; e++) acc[mt][nt][e] = 0.0f;

    unsigned aBase = (unsigned)__cvta_generic_to_shared(Asm);
    unsigned bBase = (unsigned)__cvta_generic_to_shared(Bsm);
    // ldmatrix lane addresses (element offsets *2 bytes):
    // A x4: mats = (rows0-7,k0)(rows8-15,k0)(rows0-7,k8)(rows8-15,k8)
    unsigned aAddr = aBase +
        (((unsigned)(wr * 64 + (lane & 15)) * 40 + ((lane & 16) ? 8u : 0u)) << 1);
    // B x4 per n-tile pair: mats = (nt,k0)(nt,k8)(nt+1,k0)(nt+1,k8)
    unsigned bAddr = bBase +
        (((unsigned)(wc * 32 + ((lane >> 4) & 1) * 8 + (lane & 7)) * 40 +
          ((lane & 8) ? 8u : 0u)) << 1);

    for (int k0 = 0; k0 < DDIM; k0 += 32) {
        __syncthreads();
        #pragma unroll
        for (int rep = 0; rep < 2; rep++) {
            int idx = tid + rep * 256;
            int r = idx >> 2, c = idx & 3;
            *(uint4*)&Asm[r * 40 + c * 8] =
                *(const uint4*)&g_xb[(size_t)(rowA + r) * DDIM + k0 + c * 8];
            *(uint4*)&Bsm[r * 40 + c * 8] =
                *(const uint4*)&g_xb[(size_t)(rowB + r) * DDIM + k0 + c * 8];
        }
        __syncthreads();
        #pragma unroll
        for (int s = 0; s < 2; s++) {         // two k16 steps per BK=32
            unsigned bf[4][2];
            #pragma unroll
            for (int ntp = 0; ntp < 2; ntp++) {
                unsigned r0, r1, r2, r3;
                asm volatile(
                    "ldmatrix.sync.aligned.m8n8.x4.shared.b16 {%0,%1,%2,%3}, [%4];"
                    : "=r"(r0), "=r"(r1), "=r"(r2), "=r"(r3)
                    : "r"(bAddr + (unsigned)((ntp * 16 * 40 + s * 16) * 2)));
                bf[2 * ntp][0] = r0; bf[2 * ntp][1] = r1;
                bf[2 * ntp + 1][0] = r2; bf[2 * ntp + 1][1] = r3;
            }
            #pragma unroll
            for (int mt = 0; mt < 4; mt++) {
                unsigned a0, a1, a2, a3;
                asm volatile(
                    "ldmatrix.sync.aligned.m8n8.x4.shared.b16 {%0,%1,%2,%3}, [%4];"
                    : "=r"(a0), "=r"(a1), "=r"(a2), "=r"(a3)
                    : "r"(aAddr + (unsigned)((mt * 16 * 40 + s * 16) * 2)));
                #pragma unroll
                for (int nt = 0; nt < 4; nt++) {
                    asm volatile(
                        "mma.sync.aligned.m16n8k16.row.col.f32.bf16.bf16.f32 "
                        "{%0,%1,%2,%3}, {%4,%5,%6,%7}, {%8,%9}, {%0,%1,%2,%3};"
                        : "+f"(acc[mt][nt][0]), "+f"(acc[mt][nt][1]),
                          "+f"(acc[mt][nt][2]), "+f"(acc[mt][nt][3])
                        : "r"(a0), "r"(a1), "r"(a2), "r"(a3),
                          "r"(bf[nt][0]), "r"(bf[nt][1]));
                }
            }
        }
    }

    // Spill accumulators so the epilogue loops stay rolled (threefry emitted
    // only twice, not 128x).
    float accl[64];
    #pragma unroll
    for (int mt = 0; mt < 4; mt++)
        #pragma unroll
        for (int nt = 0; nt < 4; nt++)
            #pragma unroll
            for (int e = 0; e < 4; e++)
                accl[mt * 16 + nt * 4 + e] = acc[mt][nt][e];

    float lsum = 0.0f;
    #pragma unroll 1
    for (int e = 0; e < 64; e++) {
        int mt = e >> 4, nt = (e >> 2) & 3, rh = (e >> 1) & 1, ch = e & 1;
        int il = wr * 64 + mt * 16 + g + rh * 8;        // local row in A tile
        int jl = wc * 32 + nt * 8 + 2 * t4 + ch;        // local row in B tile
        float s = accl[e];
        lsum += triplet_term(rowA + il, rowB + jl, s, DpA[il]);
        if (offDiag)
            lsum += triplet_term(rowB + jl, rowA + il, s, DpB[jl]);
    }

    // block reduction -> one atomicAdd per CTA
    #pragma unroll
    for (int o = 16; o; o >>= 1) lsum += __shfl_down_sync(0xffffffffu, lsum, o);
    if ((tid & 31) == 0) red[tid >> 5] = lsum;
    __syncthreads();
    if (tid < 8) {
        float s2 = red[tid];
        #pragma unroll
        for (int o = 4; o; o >>= 1) s2 += __shfl_down_sync(0xffu, s2, o);
        if (tid == 0) atomicAdd(out, s2);
    }
}

// ---------------------------------------------------------------------------
extern "C" void kernel_launch(void* const* d_in, const int* in_sizes, int n_in,
                              void* d_out, int out_size) {
    const float* samples = (const float*)d_in[0];
    float* out = (float*)d_out;

    normalize_kernel<<<NROWS, 256>>>(samples);
    posdist_kernel<<<NCLS, 256>>>();
    zero_kernel<<<(out_size + 255) / 256, 256>>>(out, out_size);
    dim3 grid(NROWS / 128, NROWS / 128);
    loss_kernel<<<grid, 256>>>(out);
}

// round 5
// speedup vs baseline: 5.6792x; 1.0437x over previous
#include <cuda_runtime.h>
#include <cuda_bf16.h>

// Problem constants (fixed by the dataset instance)
#define NROWS  4096
#define DDIM   1024
#define NCLS   512
#define NNEGS  3679
#define HHALF  7534592u        // n/2 for threefry lane pairing, n = 4096*3679
#define MARGINF 0.15f
#define TTILES 32              // 4096 / 128

// Scratch (static __device__ arrays: allocation-free)
__device__ float g_xn[NROWS * DDIM];            // normalized samples, fp32 (posdist)
__device__ __nv_bfloat16 g_xb[NROWS * DDIM];    // normalized samples, bf16 (gram)
__device__ float g_dpos[NROWS * 8];             // per-row positive distances

// ---------------------------------------------------------------------------
// Threefry-2x32-20, key (0, 42), exact JAX semantics.
// ---------------------------------------------------------------------------
__device__ __forceinline__ float tf_uniform(unsigned f) {
    const unsigned ks1 = 42u;
    const unsigned ks2 = 0x1BD11BDAu ^ 42u;
    unsigned lane = (f < HHALF) ? f : (f - HHALF);
    unsigned x0 = lane;
    unsigned x1 = lane + HHALF + ks1;
#define TFR(r) { x0 += x1; x1 = (x1 << (r)) | (x1 >> (32 - (r))); x1 ^= x0; }
    TFR(13) TFR(15) TFR(26) TFR(6)   x0 += ks1; x1 += ks2 + 1u;
    TFR(17) TFR(29) TFR(16) TFR(24)  x0 += ks2; x1 += 0u  + 2u;
    TFR(13) TFR(15) TFR(26) TFR(6)   x0 += 0u;  x1 += ks1 + 3u;
    TFR(17) TFR(29) TFR(16) TFR(24)  x0 += ks1; x1 += ks2 + 4u;
    TFR(13) TFR(15) TFR(26) TFR(6)   x0 += ks2; x1 += 0u  + 5u;
#undef TFR
    unsigned bits = (f < HHALF) ? x0 : x1;
    return __uint_as_float((bits >> 9) | 0x3F800000u) - 1.0f;
}

// Per-element triplet hinge term. dp points at the 8-slot positive-distance
// row for anchor i (in shared memory); s = cos(i, j).
__device__ __forceinline__ float triplet_term(int i, int j, float s,
                                              const float* __restrict__ dp) {
    int pi = 7 - (i & 7);
    int c = i >> 3, cj = j >> 3;
    if (pi == 0 || c == cj) return 0.0f;
    int dd = abs(c - cj);
    int before = max(0, c - dd) + max(0, (NCLS - 1) - c - dd)
               + ((cj > c && c >= dd) ? 1 : 0);
    int t = (before << 3) + (j & 7);
    if (t >= NNEGS) return 0.0f;
    float u = tf_uniform((unsigned)i * NNEGS + (unsigned)t);
    int ridx = min((int)(u * (float)pi), pi - 1);
    // d_pos - d_neg + M = dp + cos + (M - 1)
    return fmaxf(dp[ridx] + s + (MARGINF - 1.0f), 0.0f);
}

__device__ __forceinline__ void cp16(void* s, const void* g) {
    unsigned sa = (unsigned)__cvta_generic_to_shared(s);
    asm volatile("cp.async.cg.shared.global [%0], [%1], 16;\n" :: "r"(sa), "l"(g));
}

// ---------------------------------------------------------------------------
// Kernel 1: row L2-normalize; writes fp32 and bf16 copies. Also zeroes out.
// ---------------------------------------------------------------------------
__global__ void normalize_kernel(const float* __restrict__ x,
                                 float* __restrict__ out, int out_size) {
    int row = blockIdx.x;
    int t = threadIdx.x;
    if (row == 0 && t == 0)
        for (int i = 0; i < out_size; i++) out[i] = 0.0f;
    const float4* xin = (const float4*)(x + (size_t)row * DDIM);
    float4 v = xin[t];
    float ss = v.x * v.x + v.y * v.y + v.z * v.z + v.w * v.w;
    #pragma unroll
    for (int o = 16; o; o >>= 1) ss += __shfl_down_sync(0xffffffffu, ss, o);
    __shared__ float ws[8];
    if ((t & 31) == 0) ws[t >> 5] = ss;
    __syncthreads();
    if (t < 8) {
        float s2 = ws[t];
        #pragma unroll
        for (int o = 4; o; o >>= 1) s2 += __shfl_down_sync(0xffu, s2, o);
        if (t == 0) ws[0] = s2;
    }
    __syncthreads();
    float scale = 1.0f / fmaxf(sqrtf(ws[0]), 1e-8f);
    v.x *= scale; v.y *= scale; v.z *= scale; v.w *= scale;
    ((float4*)(g_xn + (size_t)row * DDIM))[t] = v;
    __nv_bfloat16 b[4];
    b[0] = __float2bfloat16(v.x); b[1] = __float2bfloat16(v.y);
    b[2] = __float2bfloat16(v.z); b[3] = __float2bfloat16(v.w);
    *(uint2*)(g_xb + (size_t)row * DDIM + t * 4) = *(uint2*)b;
}

// ---------------------------------------------------------------------------
// Kernel 2: positive distances within each class (fp32, exact).
// ---------------------------------------------------------------------------
__global__ void posdist_kernel() {
    int cls = blockIdx.x;
    __shared__ float sm[8][DDIM];
    int t = threadIdx.x;
    const float4* src = (const float4*)(g_xn + (size_t)cls * 8 * DDIM);
    float4* dst = (float4*)(&sm[0][0]);
    #pragma unroll
    for (int idx = t; idx < 8 * DDIM / 4; idx += 256) dst[idx] = src[idx];
    __syncthreads();
    int w = t >> 5, lane = t & 31;
    for (int q = w; q < 28; q += 8) {
        int a = 0, rem = q;
        while (rem >= 7 - a) { rem -= 7 - a; a++; }
        int b = a + 1 + rem;
        float s = 0.f;
        for (int e = lane; e < DDIM; e += 32) s += sm[a][e] * sm[b][e];
        #pragma unroll
        for (int o = 16; o; o >>= 1) s += __shfl_down_sync(0xffffffffu, s, o);
        if (lane == 0) g_dpos[(cls * 8 + a) * 8 + (b - a - 1)] = 1.0f - s;
    }
}

// ---------------------------------------------------------------------------
// Kernel 3: bf16 tensor-core Gram (triangular 1D grid, 528 CTAs; off-diagonal
// tiles first) with cp.async double-buffered mainloop + fused triplet
// epilogue applied in both orientations for off-diagonal tiles.
// CTA = 128x128 tile, 8 warps, each warp 64x32 via m16n8k16 mma.sync.
// ---------------------------------------------------------------------------
__global__ __launch_bounds__(256, 2) void loss_kernel(float* __restrict__ out) {
    // decode blockIdx.x -> (by, bx), bx >= by; off-diagonal pairs first
    int kblk = blockIdx.x;
    int by, bx;
    if (kblk < (TTILES * (TTILES - 1)) / 2) {
        int e = (int)((63.0f - sqrtf(3969.0f - 8.0f * (float)kblk)) * 0.5f);
        while ((e + 1) * (TTILES - 1) - ((e + 1) * e) / 2 <= kblk) e++;
        while (e * (TTILES - 1) - (e * (e - 1)) / 2 > kblk) e--;
        by = e;
        bx = by + 1 + (kblk - (by * (TTILES - 1) - (by * (by - 1)) / 2));
    } else {
        by = bx = kblk - (TTILES * (TTILES - 1)) / 2;
    }
    const bool offDiag = (bx != by);
    int rowA = by * 128, rowB = bx * 128;

    // 48KB static smem exactly: 2x(2x128x40 bf16) + 256x8 float
    __shared__ __align__(16) __nv_bfloat16 Asm[2][128 * 40];
    __shared__ __align__(16) __nv_bfloat16 Bsm[2][128 * 40];
    __shared__ float Dp[256][8];   // rows 0-127: A tile, 128-255: B tile

    int tid = threadIdx.x;
    int w = tid >> 5, lane = tid & 31;
    int wr = w & 1, wc = w >> 1;            // warp tile: rows wr*64, cols wc*32
    int g = lane >> 2, t4 = lane & 3;

    // stage positive-distance tables for both tiles
    {
        int r = tid >> 1, h = tid & 1;
        *(float4*)&Dp[r][h * 4] = *(const float4*)&g_dpos[(rowA + r) * 8 + h * 4];
        *(float4*)&Dp[128 + r][h * 4] = *(const float4*)&g_dpos[(rowB + r) * 8 + h * 4];
    }

    float acc[4][4][4];
    #pragma unroll
    for (int mt = 0; mt < 4; mt++)
        #pragma unroll
        for (int nt = 0; nt < 4; nt++)
            #pragma unroll
            for (int e = 0; e < 4; e++) acc[mt][nt][e] = 0.0f;

    unsigned aBase = (unsigned)__cvta_generic_to_shared(&Asm[0][0]);
    unsigned bBase = (unsigned)__cvta_generic_to_shared(&Bsm[0][0]);
    unsigned aAddr = aBase +
        (((unsigned)(wr * 64 + (lane & 15)) * 40 + ((lane & 16) ? 8u : 0u)) << 1);
    unsigned bAddr = bBase +
        (((unsigned)(wc * 32 + ((lane >> 4) & 1) * 8 + (lane & 7)) * 40 +
          ((lane & 8) ? 8u : 0u)) << 1);
    const unsigned BUFB = 128u * 40u * 2u;   // bytes per stage buffer

    // per-thread load slots: chunks tid*2, tid*2+1 of 512 16B-chunks per tile
    int lr0 = (tid * 2) >> 2,     lc0 = (tid * 2) & 3;
    int lr1 = (tid * 2 + 1) >> 2, lc1 = (tid * 2 + 1) & 3;

    const int NIT = DDIM / 32;   // 32 iterations

    // prologue: stage 0
    {
        cp16(&Asm[0][lr0 * 40 + lc0 * 8], &g_xb[(size_t)(rowA + lr0) * DDIM + lc0 * 8]);
        cp16(&Asm[0][lr1 * 40 + lc1 * 8], &g_xb[(size_t)(rowA + lr1) * DDIM + lc1 * 8]);
        cp16(&Bsm[0][lr0 * 40 + lc0 * 8], &g_xb[(size_t)(rowB + lr0) * DDIM + lc0 * 8]);
        cp16(&Bsm[0][lr1 * 40 + lc1 * 8], &g_xb[(size_t)(rowB + lr1) * DDIM + lc1 * 8]);
        asm volatile("cp.async.commit_group;\n");
    }

    for (int it = 0; it < NIT; it++) {
        if (it + 1 < NIT) {
            int k0n = (it + 1) * 32;
            int bn = (it + 1) & 1;
            cp16(&Asm[bn][lr0 * 40 + lc0 * 8], &g_xb[(size_t)(rowA + lr0) * DDIM + k0n + lc0 * 8]);
            cp16(&Asm[bn][lr1 * 40 + lc1 * 8], &g_xb[(size_t)(rowA + lr1) * DDIM + k0n + lc1 * 8]);
            cp16(&Bsm[bn][lr0 * 40 + lc0 * 8], &g_xb[(size_t)(rowB + lr0) * DDIM + k0n + lc0 * 8]);
            cp16(&Bsm[bn][lr1 * 40 + lc1 * 8], &g_xb[(size_t)(rowB + lr1) * DDIM + k0n + lc1 * 8]);
            asm volatile("cp.async.commit_group;\n");
            asm volatile("cp.async.wait_group 1;\n");
        } else {
            asm volatile("cp.async.wait_group 0;\n");
        }
        __syncthreads();

        unsigned bufOff = (unsigned)(it & 1) * BUFB;
        #pragma unroll
        for (int s = 0; s < 2; s++) {         // two k16 steps per BK=32
            unsigned bf[4][2];
            #pragma unroll
            for (int ntp = 0; ntp < 2; ntp++) {
                unsigned r0, r1, r2, r3;
                asm volatile(
                    "ldmatrix.sync.aligned.m8n8.x4.shared.b16 {%0,%1,%2,%3}, [%4];"
                    : "=r"(r0), "=r"(r1), "=r"(r2), "=r"(r3)
                    : "r"(bAddr + bufOff + (unsigned)((ntp * 16 * 40 + s * 16) * 2)));
                bf[2 * ntp][0] = r0; bf[2 * ntp][1] = r1;
                bf[2 * ntp + 1][0] = r2; bf[2 * ntp + 1][1] = r3;
            }
            #pragma unroll
            for (int mt = 0; mt < 4; mt++) {
                unsigned a0, a1, a2, a3;
                asm volatile(
                    "ldmatrix.sync.aligned.m8n8.x4.shared.b16 {%0,%1,%2,%3}, [%4];"
                    : "=r"(a0), "=r"(a1), "=r"(a2), "=r"(a3)
                    : "r"(aAddr + bufOff + (unsigned)((mt * 16 * 40 + s * 16) * 2)));
                #pragma unroll
                for (int nt = 0; nt < 4; nt++) {
                    asm volatile(
                        "mma.sync.aligned.m16n8k16.row.col.f32.bf16.bf16.f32 "
                        "{%0,%1,%2,%3}, {%4,%5,%6,%7}, {%8,%9}, {%0,%1,%2,%3};"
                        : "+f"(acc[mt][nt][0]), "+f"(acc[mt][nt][1]),
                          "+f"(acc[mt][nt][2]), "+f"(acc[mt][nt][3])
                        : "r"(a0), "r"(a1), "r"(a2), "r"(a3),
                          "r"(bf[nt][0]), "r"(bf[nt][1]));
                }
            }
        }
        __syncthreads();
    }

    // Spill accumulators so the epilogue loops stay mostly rolled.
    float accl[64];
    #pragma unroll
    for (int mt = 0; mt < 4; mt++)
        #pragma unroll
        for (int nt = 0; nt < 4; nt++)
            #pragma unroll
            for (int e = 0; e < 4; e++)
                accl[mt * 16 + nt * 4 + e] = acc[mt][nt][e];

    float lsum = 0.0f;
    #pragma unroll 2
    for (int e = 0; e < 64; e++) {
        int mt = e >> 4, nt = (e >> 2) & 3, rh = (e >> 1) & 1, ch = e & 1;
        int il = wr * 64 + mt * 16 + g + rh * 8;        // local row in A tile
        int jl = wc * 32 + nt * 8 + 2 * t4 + ch;        // local row in B tile
        float s = accl[e];
        lsum += triplet_term(rowA + il, rowB + jl, s, Dp[il]);
        if (offDiag)
            lsum += triplet_term(rowB + jl, rowA + il, s, Dp[128 + jl]);
    }

    // block reduction -> one atomicAdd per CTA (reuse Dp as scratch)
    #pragma unroll
    for (int o = 16; o; o >>= 1) lsum += __shfl_down_sync(0xffffffffu, lsum, o);
    __syncthreads();                       // everyone done reading Dp
    if ((tid & 31) == 0) Dp[0][tid >> 5] = lsum;
    __syncthreads();
    if (tid < 8) {
        float s2 = Dp[0][tid];
        #pragma unroll
        for (int o = 4; o; o >>= 1) s2 += __shfl_down_sync(0xffu, s2, o);
        if (tid == 0) atomicAdd(out, s2);
    }
}

// ---------------------------------------------------------------------------
extern "C" void kernel_launch(void* const* d_in, const int* in_sizes, int n_in,
                              void* d_out, int out_size) {
    const float* samples = (const float*)d_in[0];
    float* out = (float*)d_out;

    normalize_kernel<<<NROWS, 256>>>(samples, out, out_size);
    posdist_kernel<<<NCLS, 256>>>();
    loss_kernel<<<(TTILES * (TTILES + 1)) / 2, 256>>>(out);
}